// round 10
// baseline (speedup 1.0000x reference)
#include <cuda_runtime.h>
#include <cuda_fp16.h>
#include <cstdint>

#define DO 128
#define HD 256

// ---------------- device-global scratch ----------------
__device__ __align__(16) __half g_Bh[2][DO * 128];     // fp16(Wf^T) [type][n*K + k]
__device__ float g_sum[2 * DO];
__device__ float g_sumsq[2 * DO];
__device__ float g_scale[2 * DO];
__device__ float g_shift[2 * DO];
__device__ __align__(16) __half g_H[128000000ULL];     // h fp16

// ---------------- PTX helpers ----------------
__device__ __forceinline__ uint32_t smem_u32(const void* p) {
    uint32_t a;
    asm("{ .reg .u64 t; cvta.to.shared.u64 t, %1; cvt.u32.u64 %0, t; }" : "=r"(a) : "l"(p));
    return a;
}
__device__ __forceinline__ void ldsm4(uint32_t* r, uint32_t addr) {
    asm volatile("ldmatrix.sync.aligned.m8n8.x4.shared.b16 {%0,%1,%2,%3}, [%4];"
        : "=r"(r[0]), "=r"(r[1]), "=r"(r[2]), "=r"(r[3]) : "r"(addr));
}
__device__ __forceinline__ void mmah(float* c, const uint32_t* a, const uint32_t* b) {
    asm volatile("mma.sync.aligned.m16n8k16.row.col.f32.f16.f16.f32 "
        "{%0,%1,%2,%3}, {%4,%5,%6,%7}, {%8,%9}, {%0,%1,%2,%3};"
        : "+f"(c[0]), "+f"(c[1]), "+f"(c[2]), "+f"(c[3])
        : "r"(a[0]), "r"(a[1]), "r"(a[2]), "r"(a[3]), "r"(b[0]), "r"(b[1]));
}
__device__ __forceinline__ uint32_t pkh(float lo, float hi) {
    uint32_t r;
    asm("cvt.rn.f16x2.f32 %0, %1, %2;" : "=r"(r) : "f"(hi), "f"(lo));
    return r;
}
__device__ __forceinline__ void sts64(uint32_t addr, uint32_t a, uint32_t b) {
    asm volatile("st.shared.v2.u32 [%0], {%1, %2};" :: "r"(addr), "r"(a), "r"(b) : "memory");
}

// ---------------- fold Wf = W1@W2 -> fp16(Wf^T); bias cancels in BN ----------------
__global__ void fold_kernel(const float* __restrict__ W1, const float* __restrict__ W2,
                            int K, int type) {
    int n = blockIdx.x;
    int k = threadIdx.x;
    if (type == 0 && n == 0) {        // fused stat zeroing
        g_sum[k] = 0.f;   g_sum[k + 128] = 0.f;
        g_sumsq[k] = 0.f; g_sumsq[k + 128] = 0.f;
    }
    if (k < K) {
        const float* w1 = W1 + (size_t)k * HD;
        float acc = 0.f;
        #pragma unroll 8
        for (int h = 0; h < HD; h++) acc = fmaf(w1[h], W2[h * DO + n], acc);
        g_Bh[type][n * K + k] = __float2half_rn(acc);
    }
}

// ---------------- pass 1: GEMM (fp16, A converted at load), h -> g_H, stats ----------------
// TILE 128x128; 8 warps as 2(M) x 4(N); warp tile 64x32.
// A: one 16KB fp16 buffer, next chunk staged in registers (LDG->cvt->STS).
template<int K, int TYPE>
__global__ __launch_bounds__(256, 2)
void gemm1_kernel(const float* __restrict__ X, __half* __restrict__ H, int N, int ntiles) {
    constexpr int NCH  = K / 64;
    constexpr int STR2 = K * 2 + 16;                 // B row stride (bytes)
    constexpr int SM_A   = 0;                        // 16 KB fp16 A chunk (128r x 64k)
    constexpr int SM_STG = 16384;                    // 32 KB epilogue stage (128r x 128c fp16)
    constexpr int SM_B   = 16384 + 32768;
    constexpr int SM_STAT = SM_B + 128 * STR2;

    extern __shared__ char smc[];
    const uint32_t sb = smem_u32(smc);
    float* ssum = (float*)(smc + SM_STAT);
    float* ssq  = (float*)(smc + SM_STAT + 512);

    const int tid  = threadIdx.x;
    const int lane = tid & 31;
    const int wid  = tid >> 5;
    const int wm   = wid >> 2;                       // 0..1
    const int wn   = wid & 3;                        // 0..3

    // B -> smem once
    for (int i = tid; i < 128 * (K / 8); i += 256) {
        int n = i / (K / 8), g = i % (K / 8);
        *(uint4*)(smc + SM_B + n * STR2 + g * 16) = *(const uint4*)&g_Bh[TYPE][n * K + g * 8];
    }
    if (tid < 128) { ssum[tid] = 0.f; ssq[tid] = 0.f; }
    __syncthreads();

    // loader indices (per thread: row = tid>>1, 32-elem half kh)
    const int lrow = tid >> 1;
    const int lkh  = (tid & 1) << 5;                 // fp32 elem offset
    const uint32_t lsts = sb + SM_A + (uint32_t)(lrow * 128);
    const uint32_t lxor = (uint32_t)((lrow & 7) << 4);

    // A ldsm addressing
    const uint32_t aoff0 = (uint32_t)((lane >> 4) << 4);
    const uint32_t axor  = (uint32_t)((lane & 7) << 4);
    uint32_t abase[4];
    #pragma unroll
    for (int mt = 0; mt < 4; mt++)
        abase[mt] = sb + SM_A + (uint32_t)((wm * 64 + mt * 16 + (lane & 15)) * 128);

    // B ldsm addressing (16 n-rows per ldsm.x4)
    const uint32_t bb4 = (uint32_t)(((lane & 7) + ((lane >> 4) & 1) * 8) * STR2 + ((lane >> 3) & 1) * 16);
    const uint32_t bwarp = sb + SM_B + (uint32_t)(wn * 32 * STR2) + bb4;

    float s8[8], q8[8];
    #pragma unroll
    for (int k = 0; k < 8; k++) { s8[k] = 0.f; q8[k] = 0.f; }

    float4 R[8];
    auto ldg_chunk = [&](int tile, int c) {
        int grow = (tile << 7) + lrow;
        bool v = grow < N;
        const float* src = X + (size_t)grow * K + c * 64 + lkh;
        #pragma unroll
        for (int g = 0; g < 8; g++) {
            float4 z = make_float4(0.f, 0.f, 0.f, 0.f);
            R[g] = v ? *(const float4*)(src + g * 4) : z;
        }
    };

    int tile0 = blockIdx.x;
    if (tile0 < ntiles) ldg_chunk(tile0, 0);

    for (int tile = tile0; tile < ntiles; tile += gridDim.x) {
        float acc[4][4][4];
        #pragma unroll
        for (int mt = 0; mt < 4; mt++)
            #pragma unroll
            for (int nt = 0; nt < 4; nt++)
                #pragma unroll
                for (int j = 0; j < 4; j++) acc[mt][nt][j] = 0.f;

        #pragma unroll
        for (int c = 0; c < NCH; c++) {
            __syncthreads();               // A buffer consumers (prev chunk) done
            #pragma unroll
            for (int g = 0; g < 8; g++) {
                uint32_t byte = (uint32_t)(lkh * 2 + g * 8);
                sts64(lsts + (byte ^ lxor), pkh(R[g].x, R[g].y), pkh(R[g].z, R[g].w));
            }
            {   // issue next chunk's loads (overlap with compute below)
                int nc = c + 1, nt2 = tile;
                if (nc == NCH) { nc = 0; nt2 = tile + gridDim.x; }
                if (nt2 < ntiles) ldg_chunk(nt2, nc);
            }
            __syncthreads();               // A buffer filled

            #pragma unroll
            for (int ks = 0; ks < 4; ks++) {
                uint32_t a[4][4];
                #pragma unroll
                for (int mt = 0; mt < 4; mt++)
                    ldsm4(a[mt], abase[mt] + (((uint32_t)(ks * 32) + aoff0) ^ axor));
                uint32_t bh[2][4];
                #pragma unroll
                for (int p = 0; p < 2; p++)
                    ldsm4(bh[p], bwarp + (uint32_t)(p * 16 * STR2 + (c * 4 + ks) * 32));
                #pragma unroll
                for (int mt = 0; mt < 4; mt++) {
                    mmah(acc[mt][0], a[mt], &bh[0][0]);
                    mmah(acc[mt][1], a[mt], &bh[0][2]);
                    mmah(acc[mt][2], a[mt], &bh[1][0]);
                    mmah(acc[mt][3], a[mt], &bh[1][2]);
                }
            }
        }

        // ---- epilogue: stage fp16 h, coalesced STG + stats from rounded h ----
        {
            const int r0 = wm * 64 + (lane >> 2);
            const int cc = wn * 32 + (lane & 3) * 2;
            #pragma unroll
            for (int mt = 0; mt < 4; mt++) {
                int ra = r0 + mt * 16, rb = ra + 8;
                uint32_t xa = (uint32_t)((ra & 15) << 4);
                uint32_t xb = (uint32_t)((rb & 15) << 4);
                #pragma unroll
                for (int nt = 0; nt < 4; nt++) {
                    uint32_t cb = (uint32_t)((cc + nt * 8) * 2);
                    *(uint32_t*)(smc + SM_STG + ra * 256 + (cb ^ xa)) = pkh(acc[mt][nt][0], acc[mt][nt][1]);
                    *(uint32_t*)(smc + SM_STG + rb * 256 + (cb ^ xb)) = pkh(acc[mt][nt][2], acc[mt][nt][3]);
                }
            }
        }
        __syncthreads();
        {
            const int g = tid & 15;
            #pragma unroll
            for (int it = 0; it < 8; it++) {
                int row = (tid >> 4) + it * 16;
                uint4 v = *(const uint4*)(smc + SM_STG + row * 256
                                          + ((uint32_t)(g * 16) ^ (uint32_t)((row & 15) << 4)));
                const __half2* hv = (const __half2*)&v;
                #pragma unroll
                for (int k = 0; k < 4; k++) {
                    float2 f = __half22float2(hv[k]);
                    s8[2 * k]     += f.x;  q8[2 * k]     = fmaf(f.x, f.x, q8[2 * k]);
                    s8[2 * k + 1] += f.y;  q8[2 * k + 1] = fmaf(f.y, f.y, q8[2 * k + 1]);
                }
                int grow = (tile << 7) + row;
                if (grow < N) *(uint4*)(H + (size_t)grow * DO + g * 8) = v;
            }
        }
    }

    // ---- flush stats (col = (tid&15)*8 + k; reduce over tid>>4 pairs) ----
    #pragma unroll
    for (int k = 0; k < 8; k++) {
        s8[k] += __shfl_down_sync(0xFFFFFFFFu, s8[k], 16);
        q8[k] += __shfl_down_sync(0xFFFFFFFFu, q8[k], 16);
    }
    if (lane < 16) {
        #pragma unroll
        for (int k = 0; k < 8; k++) {
            atomicAdd(&ssum[lane * 8 + k], s8[k]);
            atomicAdd(&ssq[lane * 8 + k],  q8[k]);
        }
    }
    __syncthreads();
    if (tid < 128) {
        atomicAdd(&g_sum[TYPE * DO + tid],   ssum[tid]);
        atomicAdd(&g_sumsq[TYPE * DO + tid], ssq[tid]);
    }
}

// ---------------- finalize ----------------
__global__ void finalize_kernel(const float* __restrict__ gu, const float* __restrict__ bu,
                                const float* __restrict__ gi, const float* __restrict__ bi,
                                float invNu, float invNi) {
    int t = threadIdx.x;
    int type = t >> 7, col = t & 127;
    float invN = type ? invNi : invNu;
    float mean = g_sum[t] * invN;
    float var  = g_sumsq[t] * invN - mean * mean;
    float inv  = rsqrtf(var + 1e-5f);
    float gm = type ? gi[col] : gu[col];
    float bt = type ? bi[col] : bu[col];
    g_scale[t] = inv * gm;
    g_shift[t] = bt - mean * inv * gm;
}

// ---------------- pass 2: normalize + LeakyReLU ----------------
__global__ void norm_kernel(const __half* __restrict__ H, float* __restrict__ out,
                            long long userElems, long long total8) {
    __shared__ float sc[256], sh[256];
    int t = threadIdx.x;
    sc[t] = g_scale[t];
    sh[t] = g_shift[t];
    __syncthreads();

    long long i8 = (long long)blockIdx.x * 256 + t;
    if (i8 >= total8) return;
    long long i = i8 * 8;
    int base = (i < userElems) ? 0 : 128;
    int col  = (int)(i & 127);

    uint4 hv = __ldcs((const uint4*)(H + i));
    const __half2* h2 = (const __half2*)&hv;
    float r[8];
    #pragma unroll
    for (int k = 0; k < 4; k++) {
        float2 f = __half22float2(h2[k]);
        r[2 * k] = f.x; r[2 * k + 1] = f.y;
    }
    #pragma unroll
    for (int k = 0; k < 8; k++) {
        float h = fmaf(r[k], sc[base + col + k], sh[base + col + k]);
        r[k] = (h >= 0.f) ? h : 0.01f * h;
    }
    __stcs((float4*)(out + i),     make_float4(r[0], r[1], r[2], r[3]));
    __stcs((float4*)(out + i + 4), make_float4(r[4], r[5], r[6], r[7]));
}

// ---------------- launch ----------------
extern "C" void kernel_launch(void* const* d_in, const int* in_sizes, int n_in,
                              void* d_out, int out_size) {
    const float* x_user  = (const float*)d_in[0];
    const float* x_item  = (const float*)d_in[1];
    const float* W1_user = (const float*)d_in[2];
    const float* W1_item = (const float*)d_in[4];
    const float* W2_user = (const float*)d_in[6];
    const float* W2_item = (const float*)d_in[8];
    const float* g_user  = (const float*)d_in[10];
    const float* be_user = (const float*)d_in[11];
    const float* g_item  = (const float*)d_in[12];
    const float* be_item = (const float*)d_in[13];

    const int Nu = in_sizes[0] / 64;
    const int Ni = in_sizes[1] / 128;
    float* out = (float*)d_out;

    __half* hbuf = nullptr;
    cudaGetSymbolAddress((void**)&hbuf, g_H);

    constexpr int SM_U = 16384 + 32768 + 128 * (64 * 2 + 16) + 1024;    // ~68 KB
    constexpr int SM_I = 16384 + 32768 + 128 * (128 * 2 + 16) + 1024;   // ~84 KB
    cudaFuncSetAttribute(gemm1_kernel<64, 0>,  cudaFuncAttributeMaxDynamicSharedMemorySize, SM_U);
    cudaFuncSetAttribute(gemm1_kernel<128, 1>, cudaFuncAttributeMaxDynamicSharedMemorySize, SM_I);

    fold_kernel<<<DO, 128>>>(W1_user, W2_user, 64, 0);
    fold_kernel<<<DO, 128>>>(W1_item, W2_item, 128, 1);

    const int tiles_u = (Nu + 127) / 128;
    const int tiles_i = (Ni + 127) / 128;
    const int GRID = 296;

    gemm1_kernel<64, 0><<<(tiles_u < GRID ? tiles_u : GRID), 256, SM_U>>>(x_user, hbuf, Nu, tiles_u);
    gemm1_kernel<128, 1><<<(tiles_i < GRID ? tiles_i : GRID), 256, SM_I>>>(x_item, hbuf + (size_t)Nu * DO, Ni, tiles_i);

    finalize_kernel<<<1, 256>>>(g_user, be_user, g_item, be_item, 1.0f / (float)Nu, 1.0f / (float)Ni);

    long long total  = ((long long)Nu + (long long)Ni) * DO;
    long long total8 = total / 8;
    unsigned grid = (unsigned)((total8 + 255) / 256);
    norm_kernel<<<grid, 256>>>(hbuf, out, (long long)Nu * DO, total8);
}

// round 11
// speedup vs baseline: 1.2023x; 1.2023x over previous
#include <cuda_runtime.h>
#include <cuda_fp16.h>
#include <cstdint>

#define DO 128
#define HD 256

// ---------------- device-global scratch ----------------
__device__ __align__(16) __half g_Bh[2][DO * 128];     // fp16(Wf^T) [type][n*K + k]
__device__ float g_sum[2 * DO];
__device__ float g_sumsq[2 * DO];
__device__ float g_scale[2 * DO];
__device__ float g_shift[2 * DO];

// ---------------- PTX helpers ----------------
__device__ __forceinline__ uint32_t smem_u32(const void* p) {
    uint32_t a;
    asm("{ .reg .u64 t; cvta.to.shared.u64 t, %1; cvt.u32.u64 %0, t; }" : "=r"(a) : "l"(p));
    return a;
}
__device__ __forceinline__ void ldsm4(uint32_t* r, uint32_t addr) {
    asm volatile("ldmatrix.sync.aligned.m8n8.x4.shared.b16 {%0,%1,%2,%3}, [%4];"
        : "=r"(r[0]), "=r"(r[1]), "=r"(r[2]), "=r"(r[3]) : "r"(addr));
}
__device__ __forceinline__ void mmah(float* c, const uint32_t* a, const uint32_t* b) {
    asm volatile("mma.sync.aligned.m16n8k16.row.col.f32.f16.f16.f32 "
        "{%0,%1,%2,%3}, {%4,%5,%6,%7}, {%8,%9}, {%0,%1,%2,%3};"
        : "+f"(c[0]), "+f"(c[1]), "+f"(c[2]), "+f"(c[3])
        : "r"(a[0]), "r"(a[1]), "r"(a[2]), "r"(a[3]), "r"(b[0]), "r"(b[1]));
}
__device__ __forceinline__ uint32_t pkh(float lo, float hi) {
    uint32_t r;
    asm("cvt.rn.f16x2.f32 %0, %1, %2;" : "=r"(r) : "f"(hi), "f"(lo));
    return r;
}
__device__ __forceinline__ void cp16(uint32_t dst, const float* src, bool v) {
    int sz = v ? 16 : 0;
    asm volatile("cp.async.cg.shared.global [%0], [%1], 16, %2;"
                 :: "r"(dst), "l"(src), "r"(sz) : "memory");
}
#define CP_COMMIT() asm volatile("cp.async.commit_group;" ::: "memory")
#define CP_WAIT0()  asm volatile("cp.async.wait_group 0;" ::: "memory")

// ---------------- fold Wf = W1@W2 -> fp16(Wf^T); bias cancels in BN ----------------
__global__ void fold_kernel(const float* __restrict__ W1, const float* __restrict__ W2,
                            int K, int type) {
    int n = blockIdx.x;
    int k = threadIdx.x;
    if (type == 0 && n == 0) {
        g_sum[k] = 0.f;   g_sum[k + 128] = 0.f;
        g_sumsq[k] = 0.f; g_sumsq[k + 128] = 0.f;
    }
    if (k < K) {
        const float* w1 = W1 + (size_t)k * HD;
        float acc = 0.f;
        #pragma unroll 8
        for (int h = 0; h < HD; h++) acc = fmaf(w1[h], W2[h * DO + n], acc);
        g_Bh[type][n * K + k] = __float2half_rn(acc);
    }
}

// ============ shared mainloop pieces (4M x 2N warp layout, TILE 128x128) ============
// Per-ks per warp: 2 A fragments (LDS fp32 -> pkh), 4 B ldsm.x4, 16 MMA.

// ---------------- pass 1: stats only (no stores) ----------------
template<int K, int TYPE>
__global__ __launch_bounds__(256, 2)
void stats_kernel(const float* __restrict__ X, int N, int ntiles) {
    constexpr int NCH  = K / 64;
    constexpr int STR2 = K * 2 + 16;
    constexpr int SM_B    = 65536;
    constexpr int SM_STAT = SM_B + 128 * STR2;

    extern __shared__ char smc[];
    const uint32_t sb = smem_u32(smc);
    float* ssum = (float*)(smc + SM_STAT);
    float* ssq  = (float*)(smc + SM_STAT + 512);

    const int tid  = threadIdx.x;
    const int lane = tid & 31;
    const int wid  = tid >> 5;
    const int wm   = wid >> 1;                       // 0..3
    const int wn   = wid & 1;                        // 0..1
    const int jj   = lane & 3;
    const int r0   = wm * 32 + (lane >> 2);          // fragment rows r0(+mt*16)(+8)

    for (int i = tid; i < 128 * (K / 8); i += 256) {
        int n = i / (K / 8), g = i % (K / 8);
        *(uint4*)(smc + SM_B + n * STR2 + g * 16) = *(const uint4*)&g_Bh[TYPE][n * K + g * 8];
    }
    if (tid < 128) { ssum[tid] = 0.f; ssq[tid] = 0.f; }
    __syncthreads();

    const uint32_t bwarp = sb + SM_B
        + (uint32_t)((wn * 64 + (lane & 7) + ((lane >> 4) & 1) * 8) * STR2
                     + ((lane >> 3) & 1) * 16);

    float s[16], q[16];
    #pragma unroll
    for (int k = 0; k < 16; k++) { s[k] = 0.f; q[k] = 0.f; }

    auto prefetch = [&](int tile, int c, int buf) {
        const uint32_t ab = sb + buf * 32768;
        const int koff = c * 64;
        #pragma unroll
        for (int r8 = 0; r8 < 8; r8++) {
            int i   = tid + r8 * 256;
            int row = i >> 4;
            int cb  = (i & 15) << 4;
            int grow = (tile << 7) + row;
            bool v = grow < N;
            const float* src = v ? (X + (size_t)grow * K + koff + (cb >> 2)) : X;
            cp16(ab + (uint32_t)(row * 256) + ((uint32_t)cb ^ (uint32_t)((row & 15) << 4)), src, v);
        }
    };

    int tile0 = blockIdx.x;
    if (tile0 < ntiles) prefetch(tile0, 0, 0);
    CP_COMMIT();
    int buf = 0;

    for (int tile = tile0; tile < ntiles; tile += gridDim.x) {
        float acc[2][8][4];
        #pragma unroll
        for (int mt = 0; mt < 2; mt++)
            #pragma unroll
            for (int nt = 0; nt < 8; nt++)
                #pragma unroll
                for (int j = 0; j < 4; j++) acc[mt][nt][j] = 0.f;

        #pragma unroll
        for (int c = 0; c < NCH; c++) {
            CP_WAIT0();
            __syncthreads();
            {
                int nc = c + 1, nt2 = tile;
                if (nc == NCH) { nc = 0; nt2 = tile + gridDim.x; }
                if (nt2 < ntiles) prefetch(nt2, nc, buf ^ 1);
                CP_COMMIT();
            }
            const int abuf = buf * 32768;
            #pragma unroll
            for (int ks = 0; ks < 4; ks++) {
                const uint32_t cb = (uint32_t)(ks * 64 + jj * 8);
                uint32_t A[2][4];
                #pragma unroll
                for (int mt = 0; mt < 2; mt++) {
                    int ra = r0 + mt * 16, rb = ra + 8;
                    uint32_t xa = (uint32_t)((ra & 15) << 4);
                    uint32_t xb = (uint32_t)((rb & 15) << 4);
                    float2 x00 = *(const float2*)(smc + abuf + ra * 256 + (cb ^ xa));
                    float2 x10 = *(const float2*)(smc + abuf + rb * 256 + (cb ^ xb));
                    float2 x01 = *(const float2*)(smc + abuf + ra * 256 + ((cb + 32) ^ xa));
                    float2 x11 = *(const float2*)(smc + abuf + rb * 256 + ((cb + 32) ^ xb));
                    A[mt][0] = pkh(x00.x, x00.y);
                    A[mt][1] = pkh(x10.x, x10.y);
                    A[mt][2] = pkh(x01.x, x01.y);
                    A[mt][3] = pkh(x11.x, x11.y);
                }
                uint32_t bh[4][4];
                #pragma unroll
                for (int p = 0; p < 4; p++)
                    ldsm4(bh[p], bwarp + (uint32_t)(p * 16 * STR2 + (c * 4 + ks) * 32));
                #pragma unroll
                for (int mt = 0; mt < 2; mt++)
                    #pragma unroll
                    for (int p = 0; p < 4; p++) {
                        mmah(acc[mt][2 * p],     A[mt], &bh[p][0]);
                        mmah(acc[mt][2 * p + 1], A[mt], &bh[p][2]);
                    }
            }
            buf ^= 1;
        }

        // stats from acc (invalid rows contributed zeros)
        #pragma unroll
        for (int mt = 0; mt < 2; mt++)
            #pragma unroll
            for (int nt = 0; nt < 8; nt++)
                #pragma unroll
                for (int d = 0; d < 2; d++) {
                    float a0 = acc[mt][nt][d], a2 = acc[mt][nt][d + 2];
                    s[nt * 2 + d] += a0 + a2;
                    q[nt * 2 + d] = fmaf(a0, a0, fmaf(a2, a2, q[nt * 2 + d]));
                }
    }

    // reduce over lanes sharing jj (bits 2..4), flush
    #pragma unroll
    for (int k = 0; k < 16; k++) {
        #pragma unroll
        for (int m = 4; m <= 16; m <<= 1) {
            s[k] += __shfl_xor_sync(0xFFFFFFFFu, s[k], m);
            q[k] += __shfl_xor_sync(0xFFFFFFFFu, q[k], m);
        }
    }
    if (lane < 4) {
        #pragma unroll
        for (int k = 0; k < 16; k++) {
            int col = wn * 64 + (k >> 1) * 8 + lane * 2 + (k & 1);
            atomicAdd(&ssum[col], s[k]);
            atomicAdd(&ssq[col],  q[k]);
        }
    }
    __syncthreads();
    if (tid < 128) {
        atomicAdd(&g_sum[TYPE * DO + tid],   ssum[tid]);
        atomicAdd(&g_sumsq[TYPE * DO + tid], ssq[tid]);
    }
}

// ---------------- finalize: fold BN + gamma/beta into affine ----------------
__global__ void finalize_kernel(const float* __restrict__ gu, const float* __restrict__ bu,
                                const float* __restrict__ gi, const float* __restrict__ bi,
                                float invNu, float invNi) {
    int t = threadIdx.x;
    int type = t >> 7, col = t & 127;
    float invN = type ? invNi : invNu;
    float mean = g_sum[t] * invN;
    float var  = g_sumsq[t] * invN - mean * mean;
    float inv  = rsqrtf(var + 1e-5f);
    float gm = type ? gi[col] : gu[col];
    float bt = type ? bi[col] : bu[col];
    g_scale[t] = inv * gm;
    g_shift[t] = bt - mean * inv * gm;
}

// ---------------- pass 2: recompute GEMM, normalize + LeakyReLU, direct fp32 store ----------------
template<int K, int TYPE>
__global__ __launch_bounds__(256, 2)
void out_kernel(const float* __restrict__ X, float* __restrict__ Out, int N, int ntiles) {
    constexpr int NCH  = K / 64;
    constexpr int STR2 = K * 2 + 16;
    constexpr int SM_B  = 65536;
    constexpr int SM_SC = SM_B + 128 * STR2;
    constexpr int SM_SH = SM_SC + 512;

    extern __shared__ char smc[];
    const uint32_t sb = smem_u32(smc);

    const int tid  = threadIdx.x;
    const int lane = tid & 31;
    const int wid  = tid >> 5;
    const int wm   = wid >> 1;
    const int wn   = wid & 1;
    const int jj   = lane & 3;
    const int r0   = wm * 32 + (lane >> 2);

    for (int i = tid; i < 128 * (K / 8); i += 256) {
        int n = i / (K / 8), g = i % (K / 8);
        *(uint4*)(smc + SM_B + n * STR2 + g * 16) = *(const uint4*)&g_Bh[TYPE][n * K + g * 8];
    }
    if (tid < 128) {
        ((float*)(smc + SM_SC))[tid] = g_scale[TYPE * DO + tid];
        ((float*)(smc + SM_SH))[tid] = g_shift[TYPE * DO + tid];
    }
    __syncthreads();

    const uint32_t bwarp = sb + SM_B
        + (uint32_t)((wn * 64 + (lane & 7) + ((lane >> 4) & 1) * 8) * STR2
                     + ((lane >> 3) & 1) * 16);
    const float* scp = (const float*)(smc + SM_SC);
    const float* shp = (const float*)(smc + SM_SH);

    auto prefetch = [&](int tile, int c, int buf) {
        const uint32_t ab = sb + buf * 32768;
        const int koff = c * 64;
        #pragma unroll
        for (int r8 = 0; r8 < 8; r8++) {
            int i   = tid + r8 * 256;
            int row = i >> 4;
            int cb  = (i & 15) << 4;
            int grow = (tile << 7) + row;
            bool v = grow < N;
            const float* src = v ? (X + (size_t)grow * K + koff + (cb >> 2)) : X;
            cp16(ab + (uint32_t)(row * 256) + ((uint32_t)cb ^ (uint32_t)((row & 15) << 4)), src, v);
        }
    };

    int tile0 = blockIdx.x;
    if (tile0 < ntiles) prefetch(tile0, 0, 0);
    CP_COMMIT();
    int buf = 0;

    for (int tile = tile0; tile < ntiles; tile += gridDim.x) {
        float acc[2][8][4];
        #pragma unroll
        for (int mt = 0; mt < 2; mt++)
            #pragma unroll
            for (int nt = 0; nt < 8; nt++)
                #pragma unroll
                for (int j = 0; j < 4; j++) acc[mt][nt][j] = 0.f;

        #pragma unroll
        for (int c = 0; c < NCH; c++) {
            CP_WAIT0();
            __syncthreads();
            {
                int nc = c + 1, nt2 = tile;
                if (nc == NCH) { nc = 0; nt2 = tile + gridDim.x; }
                if (nt2 < ntiles) prefetch(nt2, nc, buf ^ 1);
                CP_COMMIT();
            }
            const int abuf = buf * 32768;
            #pragma unroll
            for (int ks = 0; ks < 4; ks++) {
                const uint32_t cb = (uint32_t)(ks * 64 + jj * 8);
                uint32_t A[2][4];
                #pragma unroll
                for (int mt = 0; mt < 2; mt++) {
                    int ra = r0 + mt * 16, rb = ra + 8;
                    uint32_t xa = (uint32_t)((ra & 15) << 4);
                    uint32_t xb = (uint32_t)((rb & 15) << 4);
                    float2 x00 = *(const float2*)(smc + abuf + ra * 256 + (cb ^ xa));
                    float2 x10 = *(const float2*)(smc + abuf + rb * 256 + (cb ^ xb));
                    float2 x01 = *(const float2*)(smc + abuf + ra * 256 + ((cb + 32) ^ xa));
                    float2 x11 = *(const float2*)(smc + abuf + rb * 256 + ((cb + 32) ^ xb));
                    A[mt][0] = pkh(x00.x, x00.y);
                    A[mt][1] = pkh(x10.x, x10.y);
                    A[mt][2] = pkh(x01.x, x01.y);
                    A[mt][3] = pkh(x11.x, x11.y);
                }
                uint32_t bh[4][4];
                #pragma unroll
                for (int p = 0; p < 4; p++)
                    ldsm4(bh[p], bwarp + (uint32_t)(p * 16 * STR2 + (c * 4 + ks) * 32));
                #pragma unroll
                for (int mt = 0; mt < 2; mt++)
                    #pragma unroll
                    for (int p = 0; p < 4; p++) {
                        mmah(acc[mt][2 * p],     A[mt], &bh[p][0]);
                        mmah(acc[mt][2 * p + 1], A[mt], &bh[p][2]);
                    }
            }
            buf ^= 1;
        }

        // epilogue: normalize + LeakyReLU, direct sector-efficient STG.64
        #pragma unroll
        for (int nt = 0; nt < 8; nt++) {
            int c0 = wn * 64 + nt * 8 + jj * 2;
            float2 sc2 = *(const float2*)(scp + c0);
            float2 sh2 = *(const float2*)(shp + c0);
            #pragma unroll
            for (int mt = 0; mt < 2; mt++) {
                int ra = (tile << 7) + r0 + mt * 16;
                int rb = ra + 8;
                if (ra < N) {
                    float o0 = fmaf(acc[mt][nt][0], sc2.x, sh2.x);
                    float o1 = fmaf(acc[mt][nt][1], sc2.y, sh2.y);
                    o0 = (o0 >= 0.f) ? o0 : 0.01f * o0;
                    o1 = (o1 >= 0.f) ? o1 : 0.01f * o1;
                    __stcs((float2*)(Out + (size_t)ra * DO + c0), make_float2(o0, o1));
                }
                if (rb < N) {
                    float o2 = fmaf(acc[mt][nt][2], sc2.x, sh2.x);
                    float o3 = fmaf(acc[mt][nt][3], sc2.y, sh2.y);
                    o2 = (o2 >= 0.f) ? o2 : 0.01f * o2;
                    o3 = (o3 >= 0.f) ? o3 : 0.01f * o3;
                    __stcs((float2*)(Out + (size_t)rb * DO + c0), make_float2(o2, o3));
                }
            }
        }
    }
}

// ---------------- launch ----------------
extern "C" void kernel_launch(void* const* d_in, const int* in_sizes, int n_in,
                              void* d_out, int out_size) {
    const float* x_user  = (const float*)d_in[0];
    const float* x_item  = (const float*)d_in[1];
    const float* W1_user = (const float*)d_in[2];
    const float* W1_item = (const float*)d_in[4];
    const float* W2_user = (const float*)d_in[6];
    const float* W2_item = (const float*)d_in[8];
    const float* g_user  = (const float*)d_in[10];
    const float* be_user = (const float*)d_in[11];
    const float* g_item  = (const float*)d_in[12];
    const float* be_item = (const float*)d_in[13];

    const int Nu = in_sizes[0] / 64;
    const int Ni = in_sizes[1] / 128;
    float* out = (float*)d_out;

    constexpr int S_SM_U = 65536 + 128 * (64 * 2 + 16) + 1024;
    constexpr int S_SM_I = 65536 + 128 * (128 * 2 + 16) + 1024;
    constexpr int O_SM_U = 65536 + 128 * (64 * 2 + 16) + 1024;
    constexpr int O_SM_I = 65536 + 128 * (128 * 2 + 16) + 1024;
    cudaFuncSetAttribute(stats_kernel<64, 0>,  cudaFuncAttributeMaxDynamicSharedMemorySize, S_SM_U);
    cudaFuncSetAttribute(stats_kernel<128, 1>, cudaFuncAttributeMaxDynamicSharedMemorySize, S_SM_I);
    cudaFuncSetAttribute(out_kernel<64, 0>,    cudaFuncAttributeMaxDynamicSharedMemorySize, O_SM_U);
    cudaFuncSetAttribute(out_kernel<128, 1>,   cudaFuncAttributeMaxDynamicSharedMemorySize, O_SM_I);

    fold_kernel<<<DO, 128>>>(W1_user, W2_user, 64, 0);
    fold_kernel<<<DO, 128>>>(W1_item, W2_item, 128, 1);

    const int tiles_u = (Nu + 127) / 128;
    const int tiles_i = (Ni + 127) / 128;
    const int GRID = 296;

    stats_kernel<64, 0><<<(tiles_u < GRID ? tiles_u : GRID), 256, S_SM_U>>>(x_user, Nu, tiles_u);
    stats_kernel<128, 1><<<(tiles_i < GRID ? tiles_i : GRID), 256, S_SM_I>>>(x_item, Ni, tiles_i);

    finalize_kernel<<<1, 256>>>(g_user, be_user, g_item, be_item, 1.0f / (float)Nu, 1.0f / (float)Ni);

    out_kernel<64, 0><<<(tiles_u < GRID ? tiles_u : GRID), 256, O_SM_U>>>(x_user, out, Nu, tiles_u);
    out_kernel<128, 1><<<(tiles_i < GRID ? tiles_i : GRID), 256, O_SM_I>>>(x_item, out + (size_t)Nu * DO, Ni, tiles_i);
}

// round 12
// speedup vs baseline: 1.2064x; 1.0035x over previous
#include <cuda_runtime.h>
#include <cuda_fp16.h>
#include <cstdint>

#define DO 128
#define HD 256

// ---------------- device-global scratch ----------------
__device__ __align__(16) __half g_Bh[2][DO * 128];     // fp16(Wf^T) [type][n*K + k]
__device__ float g_sum[2 * DO];
__device__ float g_sumsq[2 * DO];
__device__ float g_scale[2 * DO];
__device__ float g_shift[2 * DO];

// ---------------- PTX helpers ----------------
__device__ __forceinline__ uint32_t smem_u32(const void* p) {
    uint32_t a;
    asm("{ .reg .u64 t; cvta.to.shared.u64 t, %1; cvt.u32.u64 %0, t; }" : "=r"(a) : "l"(p));
    return a;
}
__device__ __forceinline__ void ldsm4(uint32_t* r, uint32_t addr) {
    asm volatile("ldmatrix.sync.aligned.m8n8.x4.shared.b16 {%0,%1,%2,%3}, [%4];"
        : "=r"(r[0]), "=r"(r[1]), "=r"(r[2]), "=r"(r[3]) : "r"(addr));
}
__device__ __forceinline__ void mmah(float* c, const uint32_t* a, const uint32_t* b) {
    asm volatile("mma.sync.aligned.m16n8k16.row.col.f32.f16.f16.f32 "
        "{%0,%1,%2,%3}, {%4,%5,%6,%7}, {%8,%9}, {%0,%1,%2,%3};"
        : "+f"(c[0]), "+f"(c[1]), "+f"(c[2]), "+f"(c[3])
        : "r"(a[0]), "r"(a[1]), "r"(a[2]), "r"(a[3]), "r"(b[0]), "r"(b[1]));
}
__device__ __forceinline__ uint32_t pkh(float lo, float hi) {
    uint32_t r;
    asm("cvt.rn.f16x2.f32 %0, %1, %2;" : "=r"(r) : "f"(hi), "f"(lo));
    return r;
}
__device__ __forceinline__ void cp16(uint32_t dst, const float* src, bool v) {
    int sz = v ? 16 : 0;
    asm volatile("cp.async.cg.shared.global [%0], [%1], 16, %2;"
                 :: "r"(dst), "l"(src), "r"(sz) : "memory");
}
#define CP_COMMIT() asm volatile("cp.async.commit_group;" ::: "memory")
#define CP_WAIT0()  asm volatile("cp.async.wait_group 0;" ::: "memory")

// ---------------- fold Wf = W1@W2 -> fp16(Wf^T); bias cancels in BN ----------------
__global__ void fold_kernel(const float* __restrict__ W1, const float* __restrict__ W2,
                            int K, int type) {
    int n = blockIdx.x;
    int k = threadIdx.x;
    if (type == 0 && n == 0) {
        g_sum[k] = 0.f;   g_sum[k + 128] = 0.f;
        g_sumsq[k] = 0.f; g_sumsq[k + 128] = 0.f;
    }
    if (k < K) {
        const float* w1 = W1 + (size_t)k * HD;
        float acc = 0.f;
        #pragma unroll 8
        for (int h = 0; h < HD; h++) acc = fmaf(w1[h], W2[h * DO + n], acc);
        g_Bh[type][n * K + k] = __float2half_rn(acc);
    }
}

// ============ shared mainloop pieces (4M x 2N warp layout, TILE 128x128) ============
// Per-ks per warp: 2 A fragments (LDS fp32 -> pkh), 4 B ldsm.x4, 16 MMA.

// ---------------- pass 1: stats only (no stores) ----------------
template<int K, int TYPE>
__global__ __launch_bounds__(256, 2)
void stats_kernel(const float* __restrict__ X, int N, int ntiles) {
    constexpr int NCH  = K / 64;
    constexpr int STR2 = K * 2 + 16;
    constexpr int SM_B    = 65536;
    constexpr int SM_STAT = SM_B + 128 * STR2;

    extern __shared__ char smc[];
    const uint32_t sb = smem_u32(smc);
    float* ssum = (float*)(smc + SM_STAT);
    float* ssq  = (float*)(smc + SM_STAT + 512);

    const int tid  = threadIdx.x;
    const int lane = tid & 31;
    const int wid  = tid >> 5;
    const int wm   = wid >> 1;                       // 0..3
    const int wn   = wid & 1;                        // 0..1
    const int jj   = lane & 3;
    const int r0   = wm * 32 + (lane >> 2);          // fragment rows r0(+mt*16)(+8)

    for (int i = tid; i < 128 * (K / 8); i += 256) {
        int n = i / (K / 8), g = i % (K / 8);
        *(uint4*)(smc + SM_B + n * STR2 + g * 16) = *(const uint4*)&g_Bh[TYPE][n * K + g * 8];
    }
    if (tid < 128) { ssum[tid] = 0.f; ssq[tid] = 0.f; }
    __syncthreads();

    const uint32_t bwarp = sb + SM_B
        + (uint32_t)((wn * 64 + (lane & 7) + ((lane >> 4) & 1) * 8) * STR2
                     + ((lane >> 3) & 1) * 16);

    float s[16], q[16];
    #pragma unroll
    for (int k = 0; k < 16; k++) { s[k] = 0.f; q[k] = 0.f; }

    auto prefetch = [&](int tile, int c, int buf) {
        const uint32_t ab = sb + buf * 32768;
        const int koff = c * 64;
        #pragma unroll
        for (int r8 = 0; r8 < 8; r8++) {
            int i   = tid + r8 * 256;
            int row = i >> 4;
            int cb  = (i & 15) << 4;
            int grow = (tile << 7) + row;
            bool v = grow < N;
            const float* src = v ? (X + (size_t)grow * K + koff + (cb >> 2)) : X;
            cp16(ab + (uint32_t)(row * 256) + ((uint32_t)cb ^ (uint32_t)((row & 15) << 4)), src, v);
        }
    };

    int tile0 = blockIdx.x;
    if (tile0 < ntiles) prefetch(tile0, 0, 0);
    CP_COMMIT();
    int buf = 0;

    for (int tile = tile0; tile < ntiles; tile += gridDim.x) {
        float acc[2][8][4];
        #pragma unroll
        for (int mt = 0; mt < 2; mt++)
            #pragma unroll
            for (int nt = 0; nt < 8; nt++)
                #pragma unroll
                for (int j = 0; j < 4; j++) acc[mt][nt][j] = 0.f;

        #pragma unroll
        for (int c = 0; c < NCH; c++) {
            CP_WAIT0();
            __syncthreads();
            {
                int nc = c + 1, nt2 = tile;
                if (nc == NCH) { nc = 0; nt2 = tile + gridDim.x; }
                if (nt2 < ntiles) prefetch(nt2, nc, buf ^ 1);
                CP_COMMIT();
            }
            const int abuf = buf * 32768;
            #pragma unroll
            for (int ks = 0; ks < 4; ks++) {
                const uint32_t cb = (uint32_t)(ks * 64 + jj * 8);
                uint32_t A[2][4];
                #pragma unroll
                for (int mt = 0; mt < 2; mt++) {
                    int ra = r0 + mt * 16, rb = ra + 8;
                    uint32_t xa = (uint32_t)((ra & 15) << 4);
                    uint32_t xb = (uint32_t)((rb & 15) << 4);
                    float2 x00 = *(const float2*)(smc + abuf + ra * 256 + (cb ^ xa));
                    float2 x10 = *(const float2*)(smc + abuf + rb * 256 + (cb ^ xb));
                    float2 x01 = *(const float2*)(smc + abuf + ra * 256 + ((cb + 32) ^ xa));
                    float2 x11 = *(const float2*)(smc + abuf + rb * 256 + ((cb + 32) ^ xb));
                    A[mt][0] = pkh(x00.x, x00.y);
                    A[mt][1] = pkh(x10.x, x10.y);
                    A[mt][2] = pkh(x01.x, x01.y);
                    A[mt][3] = pkh(x11.x, x11.y);
                }
                uint32_t bh[4][4];
                #pragma unroll
                for (int p = 0; p < 4; p++)
                    ldsm4(bh[p], bwarp + (uint32_t)(p * 16 * STR2 + (c * 4 + ks) * 32));
                #pragma unroll
                for (int mt = 0; mt < 2; mt++)
                    #pragma unroll
                    for (int p = 0; p < 4; p++) {
                        mmah(acc[mt][2 * p],     A[mt], &bh[p][0]);
                        mmah(acc[mt][2 * p + 1], A[mt], &bh[p][2]);
                    }
            }
            buf ^= 1;
        }

        // stats from acc (invalid rows contributed zeros)
        #pragma unroll
        for (int mt = 0; mt < 2; mt++)
            #pragma unroll
            for (int nt = 0; nt < 8; nt++)
                #pragma unroll
                for (int d = 0; d < 2; d++) {
                    float a0 = acc[mt][nt][d], a2 = acc[mt][nt][d + 2];
                    s[nt * 2 + d] += a0 + a2;
                    q[nt * 2 + d] = fmaf(a0, a0, fmaf(a2, a2, q[nt * 2 + d]));
                }
    }

    // reduce over lanes sharing jj (bits 2..4), flush
    #pragma unroll
    for (int k = 0; k < 16; k++) {
        #pragma unroll
        for (int m = 4; m <= 16; m <<= 1) {
            s[k] += __shfl_xor_sync(0xFFFFFFFFu, s[k], m);
            q[k] += __shfl_xor_sync(0xFFFFFFFFu, q[k], m);
        }
    }
    if (lane < 4) {
        #pragma unroll
        for (int k = 0; k < 16; k++) {
            int col = wn * 64 + (k >> 1) * 8 + lane * 2 + (k & 1);
            atomicAdd(&ssum[col], s[k]);
            atomicAdd(&ssq[col],  q[k]);
        }
    }
    __syncthreads();
    if (tid < 128) {
        atomicAdd(&g_sum[TYPE * DO + tid],   ssum[tid]);
        atomicAdd(&g_sumsq[TYPE * DO + tid], ssq[tid]);
    }
}

// ---------------- finalize: fold BN + gamma/beta into affine ----------------
__global__ void finalize_kernel(const float* __restrict__ gu, const float* __restrict__ bu,
                                const float* __restrict__ gi, const float* __restrict__ bi,
                                float invNu, float invNi) {
    int t = threadIdx.x;
    int type = t >> 7, col = t & 127;
    float invN = type ? invNi : invNu;
    float mean = g_sum[t] * invN;
    float var  = g_sumsq[t] * invN - mean * mean;
    float inv  = rsqrtf(var + 1e-5f);
    float gm = type ? gi[col] : gu[col];
    float bt = type ? bi[col] : bu[col];
    g_scale[t] = inv * gm;
    g_shift[t] = bt - mean * inv * gm;
}

// ---------------- pass 2: recompute GEMM, normalize + LeakyReLU, direct fp32 store ----------------
template<int K, int TYPE>
__global__ __launch_bounds__(256, 2)
void out_kernel(const float* __restrict__ X, float* __restrict__ Out, int N, int ntiles) {
    constexpr int NCH  = K / 64;
    constexpr int STR2 = K * 2 + 16;
    constexpr int SM_B  = 65536;
    constexpr int SM_SC = SM_B + 128 * STR2;
    constexpr int SM_SH = SM_SC + 512;

    extern __shared__ char smc[];
    const uint32_t sb = smem_u32(smc);

    const int tid  = threadIdx.x;
    const int lane = tid & 31;
    const int wid  = tid >> 5;
    const int wm   = wid >> 1;
    const int wn   = wid & 1;
    const int jj   = lane & 3;
    const int r0   = wm * 32 + (lane >> 2);

    for (int i = tid; i < 128 * (K / 8); i += 256) {
        int n = i / (K / 8), g = i % (K / 8);
        *(uint4*)(smc + SM_B + n * STR2 + g * 16) = *(const uint4*)&g_Bh[TYPE][n * K + g * 8];
    }
    if (tid < 128) {
        ((float*)(smc + SM_SC))[tid] = g_scale[TYPE * DO + tid];
        ((float*)(smc + SM_SH))[tid] = g_shift[TYPE * DO + tid];
    }
    __syncthreads();

    const uint32_t bwarp = sb + SM_B
        + (uint32_t)((wn * 64 + (lane & 7) + ((lane >> 4) & 1) * 8) * STR2
                     + ((lane >> 3) & 1) * 16);
    const float* scp = (const float*)(smc + SM_SC);
    const float* shp = (const float*)(smc + SM_SH);

    auto prefetch = [&](int tile, int c, int buf) {
        const uint32_t ab = sb + buf * 32768;
        const int koff = c * 64;
        #pragma unroll
        for (int r8 = 0; r8 < 8; r8++) {
            int i   = tid + r8 * 256;
            int row = i >> 4;
            int cb  = (i & 15) << 4;
            int grow = (tile << 7) + row;
            bool v = grow < N;
            const float* src = v ? (X + (size_t)grow * K + koff + (cb >> 2)) : X;
            cp16(ab + (uint32_t)(row * 256) + ((uint32_t)cb ^ (uint32_t)((row & 15) << 4)), src, v);
        }
    };

    int tile0 = blockIdx.x;
    if (tile0 < ntiles) prefetch(tile0, 0, 0);
    CP_COMMIT();
    int buf = 0;

    for (int tile = tile0; tile < ntiles; tile += gridDim.x) {
        float acc[2][8][4];
        #pragma unroll
        for (int mt = 0; mt < 2; mt++)
            #pragma unroll
            for (int nt = 0; nt < 8; nt++)
                #pragma unroll
                for (int j = 0; j < 4; j++) acc[mt][nt][j] = 0.f;

        #pragma unroll
        for (int c = 0; c < NCH; c++) {
            CP_WAIT0();
            __syncthreads();
            {
                int nc = c + 1, nt2 = tile;
                if (nc == NCH) { nc = 0; nt2 = tile + gridDim.x; }
                if (nt2 < ntiles) prefetch(nt2, nc, buf ^ 1);
                CP_COMMIT();
            }
            const int abuf = buf * 32768;
            #pragma unroll
            for (int ks = 0; ks < 4; ks++) {
                const uint32_t cb = (uint32_t)(ks * 64 + jj * 8);
                uint32_t A[2][4];
                #pragma unroll
                for (int mt = 0; mt < 2; mt++) {
                    int ra = r0 + mt * 16, rb = ra + 8;
                    uint32_t xa = (uint32_t)((ra & 15) << 4);
                    uint32_t xb = (uint32_t)((rb & 15) << 4);
                    float2 x00 = *(const float2*)(smc + abuf + ra * 256 + (cb ^ xa));
                    float2 x10 = *(const float2*)(smc + abuf + rb * 256 + (cb ^ xb));
                    float2 x01 = *(const float2*)(smc + abuf + ra * 256 + ((cb + 32) ^ xa));
                    float2 x11 = *(const float2*)(smc + abuf + rb * 256 + ((cb + 32) ^ xb));
                    A[mt][0] = pkh(x00.x, x00.y);
                    A[mt][1] = pkh(x10.x, x10.y);
                    A[mt][2] = pkh(x01.x, x01.y);
                    A[mt][3] = pkh(x11.x, x11.y);
                }
                uint32_t bh[4][4];
                #pragma unroll
                for (int p = 0; p < 4; p++)
                    ldsm4(bh[p], bwarp + (uint32_t)(p * 16 * STR2 + (c * 4 + ks) * 32));
                #pragma unroll
                for (int mt = 0; mt < 2; mt++)
                    #pragma unroll
                    for (int p = 0; p < 4; p++) {
                        mmah(acc[mt][2 * p],     A[mt], &bh[p][0]);
                        mmah(acc[mt][2 * p + 1], A[mt], &bh[p][2]);
                    }
            }
            buf ^= 1;
        }

        // epilogue: normalize + LeakyReLU, direct sector-efficient STG.64
        #pragma unroll
        for (int nt = 0; nt < 8; nt++) {
            int c0 = wn * 64 + nt * 8 + jj * 2;
            float2 sc2 = *(const float2*)(scp + c0);
            float2 sh2 = *(const float2*)(shp + c0);
            #pragma unroll
            for (int mt = 0; mt < 2; mt++) {
                int ra = (tile << 7) + r0 + mt * 16;
                int rb = ra + 8;
                if (ra < N) {
                    float o0 = fmaf(acc[mt][nt][0], sc2.x, sh2.x);
                    float o1 = fmaf(acc[mt][nt][1], sc2.y, sh2.y);
                    o0 = (o0 >= 0.f) ? o0 : 0.01f * o0;
                    o1 = (o1 >= 0.f) ? o1 : 0.01f * o1;
                    __stcs((float2*)(Out + (size_t)ra * DO + c0), make_float2(o0, o1));
                }
                if (rb < N) {
                    float o2 = fmaf(acc[mt][nt][2], sc2.x, sh2.x);
                    float o3 = fmaf(acc[mt][nt][3], sc2.y, sh2.y);
                    o2 = (o2 >= 0.f) ? o2 : 0.01f * o2;
                    o3 = (o3 >= 0.f) ? o3 : 0.01f * o3;
                    __stcs((float2*)(Out + (size_t)rb * DO + c0), make_float2(o2, o3));
                }
            }
        }
    }
}

// ---------------- launch ----------------
extern "C" void kernel_launch(void* const* d_in, const int* in_sizes, int n_in,
                              void* d_out, int out_size) {
    const float* x_user  = (const float*)d_in[0];
    const float* x_item  = (const float*)d_in[1];
    const float* W1_user = (const float*)d_in[2];
    const float* W1_item = (const float*)d_in[4];
    const float* W2_user = (const float*)d_in[6];
    const float* W2_item = (const float*)d_in[8];
    const float* g_user  = (const float*)d_in[10];
    const float* be_user = (const float*)d_in[11];
    const float* g_item  = (const float*)d_in[12];
    const float* be_item = (const float*)d_in[13];

    const int Nu = in_sizes[0] / 64;
    const int Ni = in_sizes[1] / 128;
    float* out = (float*)d_out;

    constexpr int S_SM_U = 65536 + 128 * (64 * 2 + 16) + 1024;
    constexpr int S_SM_I = 65536 + 128 * (128 * 2 + 16) + 1024;
    constexpr int O_SM_U = 65536 + 128 * (64 * 2 + 16) + 1024;
    constexpr int O_SM_I = 65536 + 128 * (128 * 2 + 16) + 1024;
    cudaFuncSetAttribute(stats_kernel<64, 0>,  cudaFuncAttributeMaxDynamicSharedMemorySize, S_SM_U);
    cudaFuncSetAttribute(stats_kernel<128, 1>, cudaFuncAttributeMaxDynamicSharedMemorySize, S_SM_I);
    cudaFuncSetAttribute(out_kernel<64, 0>,    cudaFuncAttributeMaxDynamicSharedMemorySize, O_SM_U);
    cudaFuncSetAttribute(out_kernel<128, 1>,   cudaFuncAttributeMaxDynamicSharedMemorySize, O_SM_I);

    fold_kernel<<<DO, 128>>>(W1_user, W2_user, 64, 0);
    fold_kernel<<<DO, 128>>>(W1_item, W2_item, 128, 1);

    const int tiles_u = (Nu + 127) / 128;
    const int tiles_i = (Ni + 127) / 128;
    const int GRID = 296;

    stats_kernel<64, 0><<<(tiles_u < GRID ? tiles_u : GRID), 256, S_SM_U>>>(x_user, Nu, tiles_u);
    stats_kernel<128, 1><<<(tiles_i < GRID ? tiles_i : GRID), 256, S_SM_I>>>(x_item, Ni, tiles_i);

    finalize_kernel<<<1, 256>>>(g_user, be_user, g_item, be_item, 1.0f / (float)Nu, 1.0f / (float)Ni);

    out_kernel<64, 0><<<(tiles_u < GRID ? tiles_u : GRID), 256, O_SM_U>>>(x_user, out, Nu, tiles_u);
    out_kernel<128, 1><<<(tiles_i < GRID ? tiles_i : GRID), 256, O_SM_I>>>(x_item, out + (size_t)Nu * DO, Ni, tiles_i);
}

// round 16
// speedup vs baseline: 1.3713x; 1.1367x over previous
#include <cuda_runtime.h>
#include <cuda_fp16.h>
#include <cstdint>

#define DO 128
#define HD 256

// ---------------- device-global scratch ----------------
__device__ __align__(16) __half g_Bh[2][DO * 128];     // fp16(Wf^T) [type][n*K + k]
__device__ float g_sum[2 * DO];
__device__ float g_sumsq[2 * DO];
__device__ float g_scale[2 * DO];
__device__ float g_shift[2 * DO];
__device__ __align__(16) __half g_H[128000000ULL];     // h fp16

// ---------------- PTX helpers ----------------
__device__ __forceinline__ uint32_t smem_u32(const void* p) {
    uint32_t a;
    asm("{ .reg .u64 t; cvta.to.shared.u64 t, %1; cvt.u32.u64 %0, t; }" : "=r"(a) : "l"(p));
    return a;
}
__device__ __forceinline__ void ldsm4(uint32_t* r, uint32_t addr) {
    asm volatile("ldmatrix.sync.aligned.m8n8.x4.shared.b16 {%0,%1,%2,%3}, [%4];"
        : "=r"(r[0]), "=r"(r[1]), "=r"(r[2]), "=r"(r[3]) : "r"(addr));
}
__device__ __forceinline__ void mmah(float* c, const uint32_t* a, const uint32_t* b) {
    asm volatile("mma.sync.aligned.m16n8k16.row.col.f32.f16.f16.f32 "
        "{%0,%1,%2,%3}, {%4,%5,%6,%7}, {%8,%9}, {%0,%1,%2,%3};"
        : "+f"(c[0]), "+f"(c[1]), "+f"(c[2]), "+f"(c[3])
        : "r"(a[0]), "r"(a[1]), "r"(a[2]), "r"(a[3]), "r"(b[0]), "r"(b[1]));
}
__device__ __forceinline__ uint32_t pkh(float lo, float hi) {
    uint32_t r;
    asm("cvt.rn.f16x2.f32 %0, %1, %2;" : "=r"(r) : "f"(hi), "f"(lo));
    return r;
}
__device__ __forceinline__ void cp16(uint32_t dst, const float* src, bool v) {
    int sz = v ? 16 : 0;
    asm volatile("cp.async.cg.shared.global [%0], [%1], 16, %2;"
                 :: "r"(dst), "l"(src), "r"(sz) : "memory");
}
#define CP_COMMIT() asm volatile("cp.async.commit_group;" ::: "memory")
#define CP_WAIT0()  asm volatile("cp.async.wait_group 0;" ::: "memory")

// ---------------- fold (both types in one launch): Wf = W1@W2 -> fp16(Wf^T) ----------------
__global__ void fold_kernel(const float* __restrict__ W1u, const float* __restrict__ W2u,
                            const float* __restrict__ W1i, const float* __restrict__ W2i) {
    int type = blockIdx.y;
    int n = blockIdx.x;
    int k = threadIdx.x;
    int K = type ? 128 : 64;
    const float* W1 = type ? W1i : W1u;
    const float* W2 = type ? W2i : W2u;
    if (type == 0 && n == 0) {        // fused stat zeroing
        g_sum[k] = 0.f;   g_sum[k + 128] = 0.f;
        g_sumsq[k] = 0.f; g_sumsq[k + 128] = 0.f;
    }
    if (k < K) {
        const float* w1 = W1 + (size_t)k * HD;
        float acc = 0.f;
        #pragma unroll 8
        for (int h = 0; h < HD; h++) acc = fmaf(w1[h], W2[h * DO + n], acc);
        g_Bh[type][n * K + k] = __float2half_rn(acc);
    }
}

// ---------------- pass 1: GEMM (single-term fp16), h -> g_H, column stats ----------------
// TILE=128 rows; 8 warps, warp = 16 rows x 128 cols; 2 CTAs/SM.  (R8 proven)
template<int K, int TYPE>
__global__ __launch_bounds__(256, 2)
void gemm1_kernel(const float* __restrict__ X, __half* __restrict__ H, int N, int ntiles) {
    constexpr int NCH  = K / 64;
    constexpr int STR2 = K * 2 + 16;
    constexpr int SM_B    = 65536;
    constexpr int SM_STAT = SM_B + 128 * STR2;

    extern __shared__ char smc[];
    const uint32_t sb = smem_u32(smc);
    float* ssum = (float*)(smc + SM_STAT);
    float* ssq  = (float*)(smc + SM_STAT + 512);

    const int tid  = threadIdx.x;
    const int lane = tid & 31;
    const int wid  = tid >> 5;
    const int jj   = lane & 3;
    const int rA   = wid * 16 + (lane >> 2);
    const uint32_t sw0 = (uint32_t)((lane >> 2) << 4);
    const uint32_t sw1 = sw0 ^ 128u;

    for (int i = tid; i < 128 * (K / 8); i += 256) {
        int n = i / (K / 8), g = i % (K / 8);
        *(uint4*)(smc + SM_B + n * STR2 + g * 16) = *(const uint4*)&g_Bh[TYPE][n * K + g * 8];
    }
    if (tid < 128) { ssum[tid] = 0.f; ssq[tid] = 0.f; }
    __syncthreads();

    const uint32_t bb4 = (uint32_t)(((lane & 7) + ((lane >> 4) & 1) * 8) * STR2 + ((lane >> 3) & 1) * 16);

    float s8[8], q8[8];
    #pragma unroll
    for (int k = 0; k < 8; k++) { s8[k] = 0.f; q8[k] = 0.f; }

    auto prefetch = [&](int tile, int c, int buf) {
        const uint32_t ab = sb + buf * 32768;
        const int koff = c * 64;
        #pragma unroll
        for (int r8 = 0; r8 < 8; r8++) {
            int i   = tid + r8 * 256;
            int row = i >> 4;
            int cb  = (i & 15) << 4;
            int grow = (tile << 7) + row;
            bool v = grow < N;
            const float* src = v ? (X + (size_t)grow * K + koff + (cb >> 2)) : X;
            cp16(ab + (uint32_t)(row * 256) + ((uint32_t)cb ^ (uint32_t)((row & 15) << 4)), src, v);
        }
    };

    int tile0 = blockIdx.x;
    if (tile0 < ntiles) prefetch(tile0, 0, 0);
    CP_COMMIT();
    int buf = 0;

    for (int tile = tile0; tile < ntiles; tile += gridDim.x) {
        float acc[16][4];
        #pragma unroll
        for (int nt = 0; nt < 16; nt++)
            #pragma unroll
            for (int j = 0; j < 4; j++) acc[nt][j] = 0.f;

        #pragma unroll
        for (int c = 0; c < NCH; c++) {
            CP_WAIT0();
            __syncthreads();
            {
                int nc = c + 1, nt2 = tile;
                if (nc == NCH) { nc = 0; nt2 = tile + gridDim.x; }
                if (nt2 < ntiles) prefetch(nt2, nc, buf ^ 1);
                CP_COMMIT();
            }
            const int abuf = buf * 32768;
            #pragma unroll
            for (int ks = 0; ks < 4; ks++) {
                const uint32_t cb = (uint32_t)(ks * 64 + jj * 8);
                float2 x00 = *(const float2*)(smc + abuf + rA * 256 + (cb ^ sw0));
                float2 x10 = *(const float2*)(smc + abuf + (rA + 8) * 256 + (cb ^ sw1));
                float2 x01 = *(const float2*)(smc + abuf + rA * 256 + ((cb + 32) ^ sw0));
                float2 x11 = *(const float2*)(smc + abuf + (rA + 8) * 256 + ((cb + 32) ^ sw1));

                uint32_t AH[4];
                AH[0] = pkh(x00.x, x00.y);
                AH[1] = pkh(x10.x, x10.y);
                AH[2] = pkh(x01.x, x01.y);
                AH[3] = pkh(x11.x, x11.y);

                const uint32_t bbase = sb + SM_B + bb4 + (uint32_t)((c * 4 + ks) * 32);
                #pragma unroll
                for (int g = 0; g < 2; g++) {
                    uint32_t bh[4][4];
                    #pragma unroll
                    for (int p = 0; p < 4; p++)
                        ldsm4(bh[p], bbase + (uint32_t)((g * 4 + p) * 16 * STR2));
                    #pragma unroll
                    for (int p = 0; p < 4; p++) {
                        mmah(acc[2 * (g * 4 + p)],     AH, &bh[p][0]);
                        mmah(acc[2 * (g * 4 + p) + 1], AH, &bh[p][2]);
                    }
                }
            }
            buf ^= 1;
        }

        // ---- epilogue: warp-private staging in the just-consumed buffer ----
        const int stb = (buf ^ 1) * 32768;
        #pragma unroll
        for (int nt = 0; nt < 16; nt++) {
            uint32_t c2 = (uint32_t)(nt * 16 + jj * 4);
            *(uint32_t*)(smc + stb + rA * 256 + (c2 ^ sw0))       = pkh(acc[nt][0], acc[nt][1]);
            *(uint32_t*)(smc + stb + (rA + 8) * 256 + (c2 ^ sw1)) = pkh(acc[nt][2], acc[nt][3]);
        }
        __syncwarp();
        #pragma unroll
        for (int i = 0; i < 8; i++) {
            int rr = wid * 16 + (lane >> 4) + i * 2;
            uint32_t c2 = (uint32_t)((lane & 15) << 4);
            uint4 v = *(const uint4*)(smc + stb + rr * 256 + (c2 ^ (uint32_t)((rr & 15) << 4)));
            const __half2* hv = (const __half2*)&v;
            #pragma unroll
            for (int k = 0; k < 4; k++) {
                float2 f = __half22float2(hv[k]);
                s8[2 * k]     += f.x;  q8[2 * k]     = fmaf(f.x, f.x, q8[2 * k]);
                s8[2 * k + 1] += f.y;  q8[2 * k + 1] = fmaf(f.y, f.y, q8[2 * k + 1]);
            }
            int grow = (tile << 7) + rr;
            if (grow < N) *(uint4*)(H + (size_t)grow * DO + (lane & 15) * 8) = v;
        }
    }

    // ---- flush stats ----
    #pragma unroll
    for (int k = 0; k < 8; k++) {
        s8[k] += __shfl_down_sync(0xFFFFFFFFu, s8[k], 16);
        q8[k] += __shfl_down_sync(0xFFFFFFFFu, q8[k], 16);
    }
    if (lane < 16) {
        #pragma unroll
        for (int k = 0; k < 8; k++) {
            atomicAdd(&ssum[lane * 8 + k], s8[k]);
            atomicAdd(&ssq[lane * 8 + k],  q8[k]);
        }
    }
    __syncthreads();
    if (tid < 128) {
        atomicAdd(&g_sum[TYPE * DO + tid],   ssum[tid]);
        atomicAdd(&g_sumsq[TYPE * DO + tid], ssq[tid]);
    }
}

// ---------------- finalize ----------------
__global__ void finalize_kernel(const float* __restrict__ gu, const float* __restrict__ bu,
                                const float* __restrict__ gi, const float* __restrict__ bi,
                                float invNu, float invNi) {
    int t = threadIdx.x;
    int type = t >> 7, col = t & 127;
    float invN = type ? invNi : invNu;
    float mean = g_sum[t] * invN;
    float var  = g_sumsq[t] * invN - mean * mean;
    float inv  = rsqrtf(var + 1e-5f);
    float gm = type ? gi[col] : gu[col];
    float bt = type ? bi[col] : bu[col];
    g_scale[t] = inv * gm;
    g_shift[t] = bt - mean * inv * gm;
}

// ---------------- pass 2: normalize + LeakyReLU, 32 elems/thread, MLP=4 ----------------
// Block covers 8192 contiguous elems (64 rows). col per thread is chunk-invariant.
__global__ void norm_kernel(const __half* __restrict__ H, float* __restrict__ out,
                            long long userElems, long long total) {
    __shared__ float sc[256], sh[256];
    int t = threadIdx.x;
    sc[t] = g_scale[t];
    sh[t] = g_shift[t];
    __syncthreads();

    long long base = (long long)blockIdx.x * 8192 + t * 8;
    const int col = (int)(base & 127);          // +2048 per chunk keeps col fixed

    // 4 independent loads first (MLP=4)
    uint4 hv[4];
    #pragma unroll
    for (int c = 0; c < 4; c++) {
        long long i = base + c * 2048;
        if (i < total) hv[c] = __ldcs((const uint4*)(H + i));
    }
    #pragma unroll
    for (int c = 0; c < 4; c++) {
        long long i = base + c * 2048;
        if (i >= total) continue;
        int off = (i < userElems) ? 0 : 128;
        const __half2* h2 = (const __half2*)&hv[c];
        float r[8];
        #pragma unroll
        for (int k = 0; k < 4; k++) {
            float2 f = __half22float2(h2[k]);
            r[2 * k] = f.x; r[2 * k + 1] = f.y;
        }
        #pragma unroll
        for (int k = 0; k < 8; k++) {
            float h = fmaf(r[k], sc[off + col + k], sh[off + col + k]);
            r[k] = (h >= 0.f) ? h : 0.01f * h;
        }
        __stcs((float4*)(out + i),     make_float4(r[0], r[1], r[2], r[3]));
        __stcs((float4*)(out + i + 4), make_float4(r[4], r[5], r[6], r[7]));
    }
}

// ---------------- launch ----------------
extern "C" void kernel_launch(void* const* d_in, const int* in_sizes, int n_in,
                              void* d_out, int out_size) {
    const float* x_user  = (const float*)d_in[0];
    const float* x_item  = (const float*)d_in[1];
    const float* W1_user = (const float*)d_in[2];
    const float* W1_item = (const float*)d_in[4];
    const float* W2_user = (const float*)d_in[6];
    const float* W2_item = (const float*)d_in[8];
    const float* g_user  = (const float*)d_in[10];
    const float* be_user = (const float*)d_in[11];
    const float* g_item  = (const float*)d_in[12];
    const float* be_item = (const float*)d_in[13];

    const int Nu = in_sizes[0] / 64;
    const int Ni = in_sizes[1] / 128;
    float* out = (float*)d_out;

    __half* hbuf = nullptr;
    cudaGetSymbolAddress((void**)&hbuf, g_H);

    constexpr int SM_U = 65536 + 128 * (64 * 2 + 16) + 1024;
    constexpr int SM_I = 65536 + 128 * (128 * 2 + 16) + 1024;
    cudaFuncSetAttribute(gemm1_kernel<64, 0>,  cudaFuncAttributeMaxDynamicSharedMemorySize, SM_U);
    cudaFuncSetAttribute(gemm1_kernel<128, 1>, cudaFuncAttributeMaxDynamicSharedMemorySize, SM_I);

    fold_kernel<<<dim3(DO, 2), 128>>>(W1_user, W2_user, W1_item, W2_item);

    const int tiles_u = (Nu + 127) / 128;
    const int tiles_i = (Ni + 127) / 128;
    const int GRID = 296;

    gemm1_kernel<64, 0><<<(tiles_u < GRID ? tiles_u : GRID), 256, SM_U>>>(x_user, hbuf, Nu, tiles_u);
    gemm1_kernel<128, 1><<<(tiles_i < GRID ? tiles_i : GRID), 256, SM_I>>>(x_item, hbuf + (size_t)Nu * DO, Ni, tiles_i);

    finalize_kernel<<<1, 256>>>(g_user, be_user, g_item, be_item, 1.0f / (float)Nu, 1.0f / (float)Ni);

    long long total = ((long long)Nu + (long long)Ni) * DO;
    unsigned grid = (unsigned)((total + 8191) / 8192);
    norm_kernel<<<grid, 256>>>(hbuf, out, (long long)Nu * DO, total);
}